// round 13
// baseline (speedup 1.0000x reference)
#include <cuda_runtime.h>
#include <cuda_bf16.h>
#include <math_constants.h>
#include <cstdint>

// FourierConv2D via DFT matmuls. ALL four GEMMs on mma.sync bf16
// split-precision (hi/lo, lo*lo dropped), cp.async double-buffered mainloop.
// CTA tile 128x64 (8 warps, 32x32 each) -> 2-4 CTAs/SM for latency coverage.

#define NF 511
#define LD 512
#define HH 256
#define CROP0 127
#define NN2 (NF*NF)

// ---- scratch (device globals) ----
__device__ __nv_bfloat16 g_A1h[LD*HH], g_A1l[LD*HH];
__device__ __nv_bfloat16 g_xTh[16*HH*HH], g_xTl[16*HH*HH];
__device__ __nv_bfloat16 g_T1rh[16*HH*HH], g_T1rl[16*HH*HH];
__device__ __nv_bfloat16 g_T1ih[16*HH*HH], g_T1il[16*HH*HH];
__device__ __nv_bfloat16 g_Ph[1024*HH], g_Pl[1024*HH];
__device__ __nv_bfloat16 g_Qh[1024*HH], g_Ql[1024*HH];
__device__ __nv_bfloat16 g_sTrh[LD*HH], g_sTrl[LD*HH];
__device__ __nv_bfloat16 g_sTih[LD*HH], g_sTil[LD*HH];
__device__ float g_Fr[16*HH*LD], g_Fi[16*HH*LD];
__device__ __nv_bfloat16 g_Hrh[32*HH*LD], g_Hrl[32*HH*LD];
__device__ __nv_bfloat16 g_Hih[32*HH*LD], g_Hil[32*HH*LD];
__device__ __nv_bfloat16 g_Brh[LD*LD], g_Bih[LD*LD], g_Brl[LD*LD], g_Bil[LD*LD];
__device__ __nv_bfloat16 g_UrTh[32*HH*HH], g_UrTl[32*HH*HH];
__device__ __nv_bfloat16 g_UiTh[32*HH*HH], g_UiTl[32*HH*HH];

// ---- helpers ----
__device__ __forceinline__ void split_bf16(float v, __nv_bfloat16 &h, __nv_bfloat16 &l) {
    h = __float2bfloat16(v);
    l = __float2bfloat16(v - __bfloat162float(h));
}
__device__ __forceinline__ void split_store(__nv_bfloat16* H, __nv_bfloat16* L,
                                            size_t idx, float v) {
    __nv_bfloat16 h, l; split_bf16(v, h, l); H[idx] = h; L[idx] = l;
}
__device__ __forceinline__ void twiddle_ab(int a, int b, float &cr, float &ci) {
    if (a >= NF || b >= NF) { cr = 0.f; ci = 0.f; return; }
    int r = (a * b) % NF;
    float ang = (-2.0f * CUDART_PI_F / (float)NF) * (float)r;
    sincosf(ang, &ci, &cr);
}

__device__ __forceinline__ uint32_t smem_u32(const void* p) {
    uint32_t a;
    asm("{ .reg .u64 t; cvta.to.shared.u64 t, %1; cvt.u32.u64 %0, t; }" : "=r"(a) : "l"(p));
    return a;
}
__device__ __forceinline__ void cp_async16(uint32_t dst, const void* src) {
    asm volatile("cp.async.cg.shared.global [%0], [%1], 16;" :: "r"(dst), "l"(src));
}
#define CP_COMMIT() asm volatile("cp.async.commit_group;" ::: "memory")
#define CP_WAIT0()  asm volatile("cp.async.wait_group 0;" ::: "memory")

__device__ __forceinline__ void ldsm_x4(uint32_t &r0, uint32_t &r1, uint32_t &r2, uint32_t &r3,
                                        uint32_t addr) {
    asm volatile("ldmatrix.sync.aligned.m8n8.x4.shared.b16 {%0,%1,%2,%3}, [%4];"
                 : "=r"(r0), "=r"(r1), "=r"(r2), "=r"(r3) : "r"(addr));
}
__device__ __forceinline__ void ldsm_x2(uint32_t &r0, uint32_t &r1, uint32_t addr) {
    asm volatile("ldmatrix.sync.aligned.m8n8.x2.shared.b16 {%0,%1}, [%2];"
                 : "=r"(r0), "=r"(r1) : "r"(addr));
}
__device__ __forceinline__ void mma_bf16(float* c, const uint32_t* a, const uint32_t* b) {
    asm volatile("mma.sync.aligned.m16n8k16.row.col.f32.bf16.bf16.f32 "
                 "{%0,%1,%2,%3}, {%4,%5,%6,%7}, {%8,%9}, {%0,%1,%2,%3};"
                 : "+f"(c[0]), "+f"(c[1]), "+f"(c[2]), "+f"(c[3])
                 : "r"(a[0]), "r"(a[1]), "r"(a[2]), "r"(a[3]), "r"(b[0]), "r"(b[1]));
}

#define KC 64
#define ROWB 144
#define TILEA (128 * ROWB)          // 18432 (A: 128 rows)
#define TILEBN (64 * ROWB)          // 9216  (B: 64 rows)
#define BUFB  (TILEA + TILEBN)      // 27648 per stage
#define MMA_SMEM (2 * BUFB + 128)   // 55424
#define NT 256                      // 8 warps: 4(m) x 2(n), 32x32 each

// Shared GEMM mainloop: C_tile(128x64), cp.async double-buffered, 1 sync/chunk.
// A loader: thread -> row t>>1 (0..127), 64B half (t&1): 4x cp.async16.
// B loader: thread -> row t>>2 (0..63), 32B quarter (t&3): 2x cp.async16.
template<int NCH, int LOG2>
__device__ __forceinline__ void gemm_loop(
    const __nv_bfloat16* const* Ablk, const __nv_bfloat16* const* Bblk,
    size_t aGbase, size_t bGbase,
    uint32_t tiles, uint32_t aSoff, uint32_t bSoff,
    uint32_t aFrag, uint32_t bFrag,
    float acc[2][4][4])
{
    {   // prologue: chunk 0 into buf 0
        const __nv_bfloat16* Ag = Ablk[0] + aGbase;
        const __nv_bfloat16* Bg = Bblk[0] + bGbase;
        uint32_t aT = tiles + aSoff;
        uint32_t bT = tiles + bSoff;
        #pragma unroll
        for (int i = 0; i < 4; i++) cp_async16(aT + i*16, Ag + i*8);
        cp_async16(bT,      Bg);
        cp_async16(bT + 16, Bg + 8);
        CP_COMMIT();
    }
    for (int c = 0; c < NCH; c++) {
        CP_WAIT0();
        __syncthreads();
        if (c + 1 < NCH) {
            const int blk = (c + 1) >> LOG2;
            const int k0  = ((c + 1) & ((1 << LOG2) - 1)) * KC;
            const __nv_bfloat16* Ag = Ablk[blk] + aGbase + k0;
            const __nv_bfloat16* Bg = Bblk[blk] + bGbase + k0;
            uint32_t aT = tiles + ((c + 1) & 1) * BUFB + aSoff;
            uint32_t bT = tiles + ((c + 1) & 1) * BUFB + bSoff;
            #pragma unroll
            for (int i = 0; i < 4; i++) cp_async16(aT + i*16, Ag + i*8);
            cp_async16(bT,      Bg);
            cp_async16(bT + 16, Bg + 8);
            CP_COMMIT();
        }
        const uint32_t aBase = tiles + (c & 1) * BUFB + aFrag;
        const uint32_t bBase = tiles + (c & 1) * BUFB + TILEA + bFrag;
        #pragma unroll
        for (int kk = 0; kk < 4; kk++) {
            uint32_t af[2][4], bf[4][2];
            #pragma unroll
            for (int mi = 0; mi < 2; mi++)
                ldsm_x4(af[mi][0], af[mi][1], af[mi][2], af[mi][3],
                        aBase + mi * (16 * ROWB) + kk * 32);
            #pragma unroll
            for (int ni = 0; ni < 4; ni++)
                ldsm_x2(bf[ni][0], bf[ni][1], bBase + ni * (8 * ROWB) + kk * 32);
            #pragma unroll
            for (int mi = 0; mi < 2; mi++)
                #pragma unroll
                for (int ni = 0; ni < 4; ni++)
                    mma_bf16(acc[mi][ni], af[mi], bf[ni]);
        }
    }
}

// Per-thread GEMM indices for 128x64 tiles, NT=256.
#define GEMM_IDX                                                             \
    const int t = threadIdx.x, lane = t & 31, wid = t >> 5;                  \
    const int wm = wid >> 1, wn = wid & 1;          /* 4x2 warp grid */      \
    const int arow = t >> 1, aseg = t & 1;                                   \
    const int brow = t >> 2, bseg = t & 3;                                   \
    const uint32_t aSoff = (uint32_t)(arow * ROWB + aseg * 64);              \
    const uint32_t bSoff = (uint32_t)(TILEA + brow * ROWB + bseg * 32);      \
    const uint32_t aFrag = (uint32_t)((wm*32 + (lane & 15)) * ROWB + (lane >> 4) * 16); \
    const uint32_t bFrag = (uint32_t)((wn*32 + (lane & 7)) * ROWB + ((lane >> 3) & 1) * 16);

#define ACC_INIT                                                             \
    float acc[2][4][4];                                                      \
    _Pragma("unroll")                                                        \
    for (int i = 0; i < 2; i++)                                              \
        _Pragma("unroll")                                                    \
        for (int j = 0; j < 4; j++)                                          \
            _Pragma("unroll")                                                \
            for (int q = 0; q < 4; q++) acc[i][j][q] = 0.f;

// ---------------------------------------------------------------------------
__global__ void __launch_bounds__(256) k_prep_binv() {
    int p = blockIdx.x * 256 + threadIdx.x;    // 512*512
    int n = p >> 9, k = p & 511;
    int row = CROP0 + ((n < 256) ? n : (n - 256));
    float tr, ti;
    twiddle_ab(row, k, tr, ti);
    float br = (n < 256) ? tr : -ti;
    float bi = (n < 256) ? ti :  tr;
    split_store(g_Brh, g_Brl, p, br);
    split_store(g_Bih, g_Bil, p, bi);
}

__global__ void __launch_bounds__(256) k_prep_pq() {
    int p = blockIdx.x * 256 + threadIdx.x;    // 1024*256
    int n = p >> 8, k = p & 255;
    if (n < 512) {
        float tr, ti;
        twiddle_ab(n, k, tr, ti);
        split_store(g_sTrh, g_sTrl, p, tr);
        split_store(g_sTih, g_sTil, p, ti);
        split_store(g_Ph, g_Pl, p, tr);
        split_store(g_Qh, g_Ql, p, -ti);
        if (n < 256) split_store(g_A1h, g_A1l, p, tr);
        else {
            float tr2, ti2;
            twiddle_ab(n - 256, k, tr2, ti2);
            split_store(g_A1h, g_A1l, p, ti2);
        }
    } else {
        float tr, ti;
        twiddle_ab(n - 512, k, tr, ti);
        split_store(g_Ph, g_Pl, p, ti);
        split_store(g_Qh, g_Ql, p, tr);
    }
}

__global__ void __launch_bounds__(256) k_prep_x(const float* __restrict__ x) {
    __shared__ float tile[32][33];
    const int bc = blockIdx.z;
    const int n10 = blockIdx.x * 32, n20 = blockIdx.y * 32;
    const float* X = x + (size_t)bc * (HH*HH);
    #pragma unroll
    for (int r = 0; r < 4; r++) {
        int n1 = n10 + threadIdx.y + r*8;
        tile[threadIdx.y + r*8][threadIdx.x] = X[(size_t)n1 * HH + n20 + threadIdx.x];
    }
    __syncthreads();
    const size_t ob = (size_t)bc * (HH*HH);
    #pragma unroll
    for (int r = 0; r < 4; r++) {
        int n2 = n20 + threadIdx.y + r*8;
        split_store(g_xTh, g_xTl, ob + (size_t)n2 * HH + n10 + threadIdx.x,
                    tile[threadIdx.x][threadIdx.y + r*8]);
    }
}

// ---------------------------------------------------------------------------
// fwd_cols: C[512, 256] = A[512, 768]*B[256, 768]^T per bc.
// grid (4 ntile, 4 mtile, 16 batch), 256 threads.
__global__ void __launch_bounds__(NT) k_fwd_cols_mma() {
    extern __shared__ char dyn_smem[];
    char* base = (char*)(((uintptr_t)dyn_smem + 127) & ~(uintptr_t)127);
    const uint32_t tiles = smem_u32(base);
    GEMM_IDX
    const int ntile = blockIdx.x, mtile = blockIdx.y, batch = blockIdx.z;

    const size_t xB = (size_t)batch * (HH * HH);
    const __nv_bfloat16* Ablk[3] = { g_A1h, g_A1l, g_A1h };
    const __nv_bfloat16* Bblk[3] = { g_xTh + xB, g_xTh + xB, g_xTl + xB };

    const size_t aGbase = (size_t)(mtile*128 + arow) * HH + aseg*32;
    const size_t bGbase = (size_t)(ntile*64 + brow) * HH + bseg*16;

    ACC_INIT
    gemm_loop<12, 2>(Ablk, Bblk, aGbase, bGbase, tiles, aSoff, bSoff, aFrag, bFrag, acc);

    const int group = lane >> 2, tid4 = lane & 3;
    const bool isR = (mtile < 2);
    __nv_bfloat16* Th = (isR ? g_T1rh : g_T1ih) + xB;
    __nv_bfloat16* Tl = (isR ? g_T1rl : g_T1il) + xB;
    const int colBase = ntile*64 + wn*32 + tid4*2;
    const int rowBase = (mtile & 1)*128 + wm*32 + group;
    #pragma unroll
    for (int mi = 0; mi < 2; mi++) {
        #pragma unroll
        for (int ni = 0; ni < 4; ni++) {
            int m = rowBase + mi*16;
            int cn = colBase + ni*8;
            split_store(Th, Tl, (size_t)m * HH + cn,           acc[mi][ni][0]);
            split_store(Th, Tl, (size_t)m * HH + cn + 1,       acc[mi][ni][1]);
            split_store(Th, Tl, (size_t)(m + 8) * HH + cn,     acc[mi][ni][2]);
            split_store(Th, Tl, (size_t)(m + 8) * HH + cn + 1, acc[mi][ni][3]);
        }
    }
}

// ---------------------------------------------------------------------------
// fwd_rows: C[256, 1024] = A[256, 1536]*B[1024, 1536]^T per bc.
// grid (16 ntile, 2 mtile, 16 batch), 256 threads.
__global__ void __launch_bounds__(NT) k_fwd_rows_mma() {
    extern __shared__ char dyn_smem[];
    char* base = (char*)(((uintptr_t)dyn_smem + 127) & ~(uintptr_t)127);
    const uint32_t tiles = smem_u32(base);
    GEMM_IDX
    const int ntile = blockIdx.x, mtile = blockIdx.y, batch = blockIdx.z;

    const size_t aB = (size_t)batch * (HH * HH);
    const __nv_bfloat16* Ablk[6] = { g_T1rh + aB, g_T1ih + aB, g_T1rl + aB,
                                     g_T1il + aB, g_T1rh + aB, g_T1ih + aB };
    const __nv_bfloat16* Bblk[6] = { g_Ph, g_Qh, g_Ph, g_Qh, g_Pl, g_Ql };

    const size_t aGbase = (size_t)(mtile*128 + arow) * HH + aseg*32;
    const size_t bGbase = (size_t)(ntile*64 + brow) * HH + bseg*16;

    ACC_INIT
    gemm_loop<24, 2>(Ablk, Bblk, aGbase, bGbase, tiles, aSoff, bSoff, aFrag, bFrag, acc);

    const int group = lane >> 2, tid4 = lane & 3;
    float* F = ((ntile < 8) ? g_Fr : g_Fi) + (size_t)batch * (HH*LD);
    const int colBase = (ntile & 7) * 64 + wn*32 + tid4*2;
    const int rowBase = mtile*128 + wm*32 + group;
    #pragma unroll
    for (int mi = 0; mi < 2; mi++) {
        #pragma unroll
        for (int ni = 0; ni < 4; ni++) {
            int m = rowBase + mi*16;
            int cn = colBase + ni*8;
            *(float2*)&F[(size_t)m * LD + cn]       = make_float2(acc[mi][ni][0], acc[mi][ni][1]);
            *(float2*)&F[(size_t)(m + 8) * LD + cn] = make_float2(acc[mi][ni][2], acc[mi][ni][3]);
        }
    }
}

// ---------------------------------------------------------------------------
// Einsum with Hermitian weight projection; outputs split-bf16 H.
__global__ void __launch_bounds__(256) k_einsum_h(const float* __restrict__ w) {
    int k2 = blockIdx.x * 256 + threadIdx.x;       // 0..511
    int k1 = blockIdx.y;                           // 0..255
    if (k2 == 511) {
        #pragma unroll
        for (int bo = 0; bo < 32; bo++) {
            int idx = bo * (HH*LD) + k1 * LD + 511;
            g_Hrh[idx] = __float2bfloat16(0.f); g_Hrl[idx] = __float2bfloat16(0.f);
            g_Hih[idx] = __float2bfloat16(0.f); g_Hil[idx] = __float2bfloat16(0.f);
        }
        return;
    }
    float fr[16], fi[16];
    {
        int off = k1 * LD + k2;
        #pragma unroll
        for (int bc = 0; bc < 16; bc++) {
            fr[bc] = g_Fr[bc * (HH*LD) + off];
            fi[bc] = g_Fi[bc * (HH*LD) + off];
        }
    }
    const int m1 = (k1 == 0) ? 0 : (NF - k1);
    const int m2 = (k2 == 0) ? 0 : (NF - k2);
    const int wbase  = (k1 * NF + k2) * 2;
    const int wmbase = (m1 * NF + m2) * 2;
    const float s = (k1 == 0) ? 0.5f : 1.0f;
    const int hidx = k1 * LD + k2;
    #pragma unroll
    for (int o = 0; o < 8; o++) {
        float whr[4], whi[4];
        #pragma unroll
        for (int cc = 0; cc < 4; cc++) {
            int base  = (o * 4 + cc) * (NN2 * 2);
            float w1r = w[base + wbase],  w1i = w[base + wbase + 1];
            float w2r = w[base + wmbase], w2i = w[base + wmbase + 1];
            whr[cc] = s * (w1r + w2r);
            whi[cc] = s * (w1i - w2i);
        }
        #pragma unroll
        for (int b = 0; b < 4; b++) {
            float ar = 0.f, ai = 0.f;
            #pragma unroll
            for (int cc = 0; cc < 4; cc++) {
                float xr = fr[b*4+cc], xi = fi[b*4+cc];
                ar += xr * whr[cc] - xi * whi[cc];
                ai += xr * whi[cc] + xi * whr[cc];
            }
            int idx = (b * 8 + o) * (HH*LD) + hidx;
            split_store(g_Hrh, g_Hrl, idx, ar);
            split_store(g_Hih, g_Hil, idx, ai);
        }
    }
}

// ---------------------------------------------------------------------------
// inv_u: C[256, 512] = A[256, 3072]*B[512, 3072]^T per bo; transposed U out.
// grid (8 ntile, 2 mtile, 32 batch), 256 threads.
__global__ void __launch_bounds__(NT) k_inv_u_mma() {
    extern __shared__ char dyn_smem[];
    char* base = (char*)(((uintptr_t)dyn_smem + 127) & ~(uintptr_t)127);
    const uint32_t tiles = smem_u32(base);
    GEMM_IDX
    const int ntile = blockIdx.x, mtile = blockIdx.y, batch = blockIdx.z;

    const size_t hB = (size_t)batch * (HH * LD);
    const __nv_bfloat16* Ablk[6] = { g_Hrh + hB, g_Hih + hB, g_Hrl + hB,
                                     g_Hil + hB, g_Hrh + hB, g_Hih + hB };
    const __nv_bfloat16* Bblk[6] = { g_Brh, g_Bih, g_Brh, g_Bih, g_Brl, g_Bil };

    const size_t aGbase = (size_t)(mtile*128 + arow) * LD + aseg*32;
    const size_t bGbase = (size_t)(ntile*64 + brow) * LD + bseg*16;

    ACC_INIT
    gemm_loop<48, 3>(Ablk, Bblk, aGbase, bGbase, tiles, aSoff, bSoff, aFrag, bFrag, acc);

    const int group = lane >> 2, tid4 = lane & 3;
    const bool isR = (ntile < 4);
    __nv_bfloat16* Th = (isR ? g_UrTh : g_UiTh) + (size_t)batch * (HH*HH);
    __nv_bfloat16* Tl = (isR ? g_UrTl : g_UiTl) + (size_t)batch * (HH*HH);
    const int colBase = (ntile & 3) * 64 + wn*32 + tid4*2;
    const int rowBase = mtile*128 + wm*32 + group;
    #pragma unroll
    for (int mi = 0; mi < 2; mi++) {
        #pragma unroll
        for (int ni = 0; ni < 4; ni++) {
            int m = rowBase + mi*16;
            int cn = colBase + ni*8;
            split_store(Th, Tl, (size_t)cn * HH + m,           acc[mi][ni][0]);
            split_store(Th, Tl, (size_t)(cn + 1) * HH + m,     acc[mi][ni][1]);
            split_store(Th, Tl, (size_t)cn * HH + m + 8,       acc[mi][ni][2]);
            split_store(Th, Tl, (size_t)(cn + 1) * HH + m + 8, acc[mi][ni][3]);
        }
    }
}

// ---------------------------------------------------------------------------
// k_out: out = scale * (A[256,1536]*B[256,1536]^T) + bias.
// grid (4 ntile, 2 mtile, 32 batch), 256 threads.
__global__ void __launch_bounds__(NT) k_out_mma(const float* __restrict__ bias,
                                               float* __restrict__ out) {
    extern __shared__ char dyn_smem[];
    char* base = (char*)(((uintptr_t)dyn_smem + 127) & ~(uintptr_t)127);
    const uint32_t tiles = smem_u32(base);
    GEMM_IDX
    const int ntile = blockIdx.x, mtile = blockIdx.y, batch = blockIdx.z;
    const float scale = 1.0f / ((float)NF * (float)NF);
    const float bias_v = bias[batch & 7];

    const size_t uB = (size_t)batch * (HH * HH);
    const __nv_bfloat16* Ablk[6] = { g_sTrh, g_sTih, g_sTrl, g_sTil, g_sTrh, g_sTih };
    const __nv_bfloat16* Bblk[6] = { g_UrTh + uB, g_UiTh + uB, g_UrTh + uB,
                                     g_UiTh + uB, g_UrTl + uB, g_UiTl + uB };

    const size_t aGbase = (size_t)(CROP0 + mtile*128 + arow) * HH + aseg*32;
    const size_t bGbase = (size_t)(ntile*64 + brow) * HH + bseg*16;

    ACC_INIT
    gemm_loop<24, 2>(Ablk, Bblk, aGbase, bGbase, tiles, aSoff, bSoff, aFrag, bFrag, acc);

    const int group = lane >> 2, tid4 = lane & 3;
    float* C = out + (size_t)batch * (HH*HH);
    const int colBase = ntile*64 + wn*32 + tid4*2;
    const int rowBase = mtile*128 + wm*32 + group;
    #pragma unroll
    for (int mi = 0; mi < 2; mi++) {
        #pragma unroll
        for (int ni = 0; ni < 4; ni++) {
            int m = rowBase + mi*16;
            int cn = colBase + ni*8;
            *(float2*)&C[(size_t)m * HH + cn] =
                make_float2(acc[mi][ni][0]*scale + bias_v, acc[mi][ni][1]*scale + bias_v);
            *(float2*)&C[(size_t)(m + 8) * HH + cn] =
                make_float2(acc[mi][ni][2]*scale + bias_v, acc[mi][ni][3]*scale + bias_v);
        }
    }
}

// ---------------------------------------------------------------------------
extern "C" void kernel_launch(void* const* d_in, const int* in_sizes, int n_in,
                              void* d_out, int out_size) {
    const float* im   = (const float*)d_in[0];   // (4,4,256,256)
    const float* wgt  = (const float*)d_in[1];   // (8,4,511,511,2)
    const float* bias = (const float*)d_in[2];   // (8,1,1)
    float* out = (float*)d_out;                  // (4,8,256,256)

    static int smem_set = 0;
    if (!smem_set) {
        cudaFuncSetAttribute(k_fwd_cols_mma, cudaFuncAttributeMaxDynamicSharedMemorySize, MMA_SMEM);
        cudaFuncSetAttribute(k_fwd_rows_mma, cudaFuncAttributeMaxDynamicSharedMemorySize, MMA_SMEM);
        cudaFuncSetAttribute(k_inv_u_mma,    cudaFuncAttributeMaxDynamicSharedMemorySize, MMA_SMEM);
        cudaFuncSetAttribute(k_out_mma,      cudaFuncAttributeMaxDynamicSharedMemorySize, MMA_SMEM);
        smem_set = 1;
    }

    k_prep_binv   <<<(LD * LD) / 256, 256>>>();
    k_prep_pq     <<<(1024 * HH) / 256, 256>>>();
    k_prep_x      <<<dim3(8, 8, 16), dim3(32, 8)>>>(im);
    k_fwd_cols_mma<<<dim3(4, 4, 16),  NT, MMA_SMEM>>>();
    k_fwd_rows_mma<<<dim3(16, 2, 16), NT, MMA_SMEM>>>();
    k_einsum_h    <<<dim3(2, 256),    256>>>(wgt);
    k_inv_u_mma   <<<dim3(8, 2, 32),  NT, MMA_SMEM>>>();
    k_out_mma     <<<dim3(4, 2, 32),  NT, MMA_SMEM>>>(bias, out);
}

// round 14
// speedup vs baseline: 1.2734x; 1.2734x over previous
#include <cuda_runtime.h>
#include <cuda_bf16.h>
#include <math_constants.h>
#include <cstdint>

// FourierConv2D via DFT matmuls. ALL four GEMMs on mma.sync bf16
// split-precision (hi/lo, lo*lo dropped), cp.async 3-stage pipelined mainloop,
// 512 threads / 16 warps per CTA (32x32 per warp), 128x128 CTA tiles.

#define NF 511
#define LD 512
#define HH 256
#define CROP0 127
#define NN2 (NF*NF)

// ---- scratch (device globals) ----
__device__ __nv_bfloat16 g_A1h[LD*HH], g_A1l[LD*HH];
__device__ __nv_bfloat16 g_xTh[16*HH*HH], g_xTl[16*HH*HH];
__device__ __nv_bfloat16 g_T1rh[16*HH*HH], g_T1rl[16*HH*HH];
__device__ __nv_bfloat16 g_T1ih[16*HH*HH], g_T1il[16*HH*HH];
__device__ __nv_bfloat16 g_Ph[1024*HH], g_Pl[1024*HH];
__device__ __nv_bfloat16 g_Qh[1024*HH], g_Ql[1024*HH];
__device__ __nv_bfloat16 g_sTrh[LD*HH], g_sTrl[LD*HH];
__device__ __nv_bfloat16 g_sTih[LD*HH], g_sTil[LD*HH];
__device__ float g_Fr[16*HH*LD], g_Fi[16*HH*LD];
__device__ __nv_bfloat16 g_Hrh[32*HH*LD], g_Hrl[32*HH*LD];
__device__ __nv_bfloat16 g_Hih[32*HH*LD], g_Hil[32*HH*LD];
__device__ __nv_bfloat16 g_Brh[LD*LD], g_Bih[LD*LD], g_Brl[LD*LD], g_Bil[LD*LD];
__device__ __nv_bfloat16 g_UrTh[32*HH*HH], g_UrTl[32*HH*HH];
__device__ __nv_bfloat16 g_UiTh[32*HH*HH], g_UiTl[32*HH*HH];

// ---- helpers ----
__device__ __forceinline__ void split_bf16(float v, __nv_bfloat16 &h, __nv_bfloat16 &l) {
    h = __float2bfloat16(v);
    l = __float2bfloat16(v - __bfloat162float(h));
}
__device__ __forceinline__ void split_store(__nv_bfloat16* H, __nv_bfloat16* L,
                                            size_t idx, float v) {
    __nv_bfloat16 h, l; split_bf16(v, h, l); H[idx] = h; L[idx] = l;
}
__device__ __forceinline__ void twiddle_ab(int a, int b, float &cr, float &ci) {
    if (a >= NF || b >= NF) { cr = 0.f; ci = 0.f; return; }
    int r = (a * b) % NF;
    float ang = (-2.0f * CUDART_PI_F / (float)NF) * (float)r;
    sincosf(ang, &ci, &cr);
}

__device__ __forceinline__ uint32_t smem_u32(const void* p) {
    uint32_t a;
    asm("{ .reg .u64 t; cvta.to.shared.u64 t, %1; cvt.u32.u64 %0, t; }" : "=r"(a) : "l"(p));
    return a;
}
__device__ __forceinline__ void cp_async16(uint32_t dst, const void* src) {
    asm volatile("cp.async.cg.shared.global [%0], [%1], 16;" :: "r"(dst), "l"(src));
}
#define CP_COMMIT() asm volatile("cp.async.commit_group;" ::: "memory")
#define CP_WAIT0()  asm volatile("cp.async.wait_group 0;" ::: "memory")
#define CP_WAIT1()  asm volatile("cp.async.wait_group 1;" ::: "memory")

__device__ __forceinline__ void ldsm_x4(uint32_t &r0, uint32_t &r1, uint32_t &r2, uint32_t &r3,
                                        uint32_t addr) {
    asm volatile("ldmatrix.sync.aligned.m8n8.x4.shared.b16 {%0,%1,%2,%3}, [%4];"
                 : "=r"(r0), "=r"(r1), "=r"(r2), "=r"(r3) : "r"(addr));
}
__device__ __forceinline__ void ldsm_x2(uint32_t &r0, uint32_t &r1, uint32_t addr) {
    asm volatile("ldmatrix.sync.aligned.m8n8.x2.shared.b16 {%0,%1}, [%2];"
                 : "=r"(r0), "=r"(r1) : "r"(addr));
}
__device__ __forceinline__ void mma_bf16(float* c, const uint32_t* a, const uint32_t* b) {
    asm volatile("mma.sync.aligned.m16n8k16.row.col.f32.bf16.bf16.f32 "
                 "{%0,%1,%2,%3}, {%4,%5,%6,%7}, {%8,%9}, {%0,%1,%2,%3};"
                 : "+f"(c[0]), "+f"(c[1]), "+f"(c[2]), "+f"(c[3])
                 : "r"(a[0]), "r"(a[1]), "r"(a[2]), "r"(a[3]), "r"(b[0]), "r"(b[1]));
}

#define KC 64
#define ROWB 144
#define TILEB (128 * ROWB)          // 18432 per operand tile
#define BUFB  (2 * TILEB)           // 36864 per stage (A + B)
#define NSTAGE 3
#define MMA_SMEM (NSTAGE * BUFB + 128)   // 110720
#define NT 512                      // 16 warps: 4x4 grid, 32x32 tile each

// Shared GEMM mainloop: C_tile(128x128), 16 warps, cp.async 3-stage pipeline.
// Thread t loads row t>>2 (0..127), 32B segment (t&3) of both A and B rows.
template<int NCH, int LOG2>
__device__ __forceinline__ void gemm_loop(
    const __nv_bfloat16* const* Ablk, const __nv_bfloat16* const* Bblk,
    size_t aGbase, size_t bGbase,
    uint32_t tiles, uint32_t sOff, uint32_t aFrag, uint32_t bFrag,
    float acc[2][4][4])
{
    auto issue = [&](int cc) {
        const int blk = cc >> LOG2;
        const int k0  = (cc & ((1 << LOG2) - 1)) * KC;
        const __nv_bfloat16* Ag = Ablk[blk] + aGbase + k0;
        const __nv_bfloat16* Bg = Bblk[blk] + bGbase + k0;
        uint32_t aT = tiles + (cc % NSTAGE) * BUFB + sOff;
        uint32_t bT = aT + TILEB;
        cp_async16(aT,      Ag);
        cp_async16(aT + 16, Ag + 8);
        cp_async16(bT,      Bg);
        cp_async16(bT + 16, Bg + 8);
        CP_COMMIT();
    };
    issue(0);
    issue(1);
    for (int c = 0; c < NCH; c++) {
        if (c + 1 < NCH) CP_WAIT1();
        else             CP_WAIT0();
        __syncthreads();
        if (c + 2 < NCH) issue(c + 2);
        const uint32_t aBase = tiles + (c % NSTAGE) * BUFB + aFrag;
        const uint32_t bBase = tiles + (c % NSTAGE) * BUFB + TILEB + bFrag;
        #pragma unroll
        for (int kk = 0; kk < 4; kk++) {
            uint32_t af[2][4], bf[4][2];
            #pragma unroll
            for (int mi = 0; mi < 2; mi++)
                ldsm_x4(af[mi][0], af[mi][1], af[mi][2], af[mi][3],
                        aBase + mi * (16 * ROWB) + kk * 32);
            #pragma unroll
            for (int ni = 0; ni < 4; ni++)
                ldsm_x2(bf[ni][0], bf[ni][1], bBase + ni * (8 * ROWB) + kk * 32);
            #pragma unroll
            for (int mi = 0; mi < 2; mi++)
                #pragma unroll
                for (int ni = 0; ni < 4; ni++)
                    mma_bf16(acc[mi][ni], af[mi], bf[ni]);
        }
    }
}

// Per-thread GEMM indices for NT=512 blocks, 128x128 tiles.
#define GEMM_IDX                                                             \
    const int t = threadIdx.x, lane = t & 31, wid = t >> 5;                  \
    const int wm = wid >> 2, wn = wid & 3;          /* 4x4 warp grid */      \
    const int grow = t >> 2, gseg = t & 3;                                   \
    const uint32_t sOff = (uint32_t)(grow * ROWB + gseg * 32);               \
    const uint32_t aFrag = (uint32_t)((wm*32 + (lane & 15)) * ROWB + (lane >> 4) * 16); \
    const uint32_t bFrag = (uint32_t)((wn*32 + (lane & 7)) * ROWB + ((lane >> 3) & 1) * 16);

#define ACC_INIT                                                             \
    float acc[2][4][4];                                                      \
    _Pragma("unroll")                                                        \
    for (int i = 0; i < 2; i++)                                              \
        _Pragma("unroll")                                                    \
        for (int j = 0; j < 4; j++)                                          \
            _Pragma("unroll")                                                \
            for (int q = 0; q < 4; q++) acc[i][j][q] = 0.f;

// ---------------------------------------------------------------------------
// Merged operand prep: ids [0, 262144) -> inv_u B operand (512x512),
// ids [262144, 524288) -> P/Q + split twiddle + A1 (1024x256).
__global__ void __launch_bounds__(256) k_prep_ops() {
    int gid = blockIdx.x * 256 + threadIdx.x;
    if (gid < 262144) {
        int p = gid;                        // 512*512
        int n = p >> 9, k = p & 511;
        int row = CROP0 + ((n < 256) ? n : (n - 256));
        float tr, ti;
        twiddle_ab(row, k, tr, ti);
        float br = (n < 256) ? tr : -ti;
        float bi = (n < 256) ? ti :  tr;
        split_store(g_Brh, g_Brl, p, br);
        split_store(g_Bih, g_Bil, p, bi);
    } else {
        int p = gid - 262144;               // 1024*256
        int n = p >> 8, k = p & 255;
        if (n < 512) {
            float tr, ti;
            twiddle_ab(n, k, tr, ti);
            split_store(g_sTrh, g_sTrl, p, tr);
            split_store(g_sTih, g_sTil, p, ti);
            split_store(g_Ph, g_Pl, p, tr);
            split_store(g_Qh, g_Ql, p, -ti);
            if (n < 256) split_store(g_A1h, g_A1l, p, tr);
            else {
                float tr2, ti2;
                twiddle_ab(n - 256, k, tr2, ti2);
                split_store(g_A1h, g_A1l, p, ti2);
            }
        } else {
            float tr, ti;
            twiddle_ab(n - 512, k, tr, ti);
            split_store(g_Ph, g_Pl, p, ti);
            split_store(g_Qh, g_Ql, p, tr);
        }
    }
}

__global__ void __launch_bounds__(256) k_prep_x(const float* __restrict__ x) {
    __shared__ float tile[32][33];
    const int bc = blockIdx.z;
    const int n10 = blockIdx.x * 32, n20 = blockIdx.y * 32;
    const float* X = x + (size_t)bc * (HH*HH);
    #pragma unroll
    for (int r = 0; r < 4; r++) {
        int n1 = n10 + threadIdx.y + r*8;
        tile[threadIdx.y + r*8][threadIdx.x] = X[(size_t)n1 * HH + n20 + threadIdx.x];
    }
    __syncthreads();
    const size_t ob = (size_t)bc * (HH*HH);
    #pragma unroll
    for (int r = 0; r < 4; r++) {
        int n2 = n20 + threadIdx.y + r*8;
        split_store(g_xTh, g_xTl, ob + (size_t)n2 * HH + n10 + threadIdx.x,
                    tile[threadIdx.x][threadIdx.y + r*8]);
    }
}

// ---------------------------------------------------------------------------
// fwd_cols: C[512, 256] = A[512, 768]*B[256, 768]^T per bc.
// grid (2 ntile, 4 mtile, 16 batch), 512 threads.
__global__ void __launch_bounds__(NT) k_fwd_cols_mma() {
    extern __shared__ char dyn_smem[];
    char* base = (char*)(((uintptr_t)dyn_smem + 127) & ~(uintptr_t)127);
    const uint32_t tiles = smem_u32(base);
    GEMM_IDX
    const int ntile = blockIdx.x, mtile = blockIdx.y, batch = blockIdx.z;

    const size_t xB = (size_t)batch * (HH * HH);
    const __nv_bfloat16* Ablk[3] = { g_A1h, g_A1l, g_A1h };
    const __nv_bfloat16* Bblk[3] = { g_xTh + xB, g_xTh + xB, g_xTl + xB };

    const size_t aGbase = (size_t)(mtile*128 + grow) * HH + gseg*16;
    const size_t bGbase = (size_t)(ntile*128 + grow) * HH + gseg*16;

    ACC_INIT
    gemm_loop<12, 2>(Ablk, Bblk, aGbase, bGbase, tiles, sOff, aFrag, bFrag, acc);

    const int group = lane >> 2, tid4 = lane & 3;
    const bool isR = (mtile < 2);
    __nv_bfloat16* Th = (isR ? g_T1rh : g_T1ih) + xB;
    __nv_bfloat16* Tl = (isR ? g_T1rl : g_T1il) + xB;
    const int colBase = ntile*128 + wn*32 + tid4*2;
    const int rowBase = (mtile & 1)*128 + wm*32 + group;
    #pragma unroll
    for (int mi = 0; mi < 2; mi++) {
        #pragma unroll
        for (int ni = 0; ni < 4; ni++) {
            int m = rowBase + mi*16;
            int cn = colBase + ni*8;
            split_store(Th, Tl, (size_t)m * HH + cn,           acc[mi][ni][0]);
            split_store(Th, Tl, (size_t)m * HH + cn + 1,       acc[mi][ni][1]);
            split_store(Th, Tl, (size_t)(m + 8) * HH + cn,     acc[mi][ni][2]);
            split_store(Th, Tl, (size_t)(m + 8) * HH + cn + 1, acc[mi][ni][3]);
        }
    }
}

// ---------------------------------------------------------------------------
// fwd_rows: C[256, 1024] = A[256, 1536]*B[1024, 1536]^T per bc.
// grid (8 ntile, 2 mtile, 16 batch), 512 threads.
__global__ void __launch_bounds__(NT) k_fwd_rows_mma() {
    extern __shared__ char dyn_smem[];
    char* base = (char*)(((uintptr_t)dyn_smem + 127) & ~(uintptr_t)127);
    const uint32_t tiles = smem_u32(base);
    GEMM_IDX
    const int ntile = blockIdx.x, mtile = blockIdx.y, batch = blockIdx.z;

    const size_t aB = (size_t)batch * (HH * HH);
    const __nv_bfloat16* Ablk[6] = { g_T1rh + aB, g_T1ih + aB, g_T1rl + aB,
                                     g_T1il + aB, g_T1rh + aB, g_T1ih + aB };
    const __nv_bfloat16* Bblk[6] = { g_Ph, g_Qh, g_Ph, g_Qh, g_Pl, g_Ql };

    const size_t aGbase = (size_t)(mtile*128 + grow) * HH + gseg*16;
    const size_t bGbase = (size_t)(ntile*128 + grow) * HH + gseg*16;

    ACC_INIT
    gemm_loop<24, 2>(Ablk, Bblk, aGbase, bGbase, tiles, sOff, aFrag, bFrag, acc);

    const int group = lane >> 2, tid4 = lane & 3;
    float* F = ((ntile < 4) ? g_Fr : g_Fi) + (size_t)batch * (HH*LD);
    const int colBase = (ntile & 3) * 128 + wn*32 + tid4*2;
    const int rowBase = mtile*128 + wm*32 + group;
    #pragma unroll
    for (int mi = 0; mi < 2; mi++) {
        #pragma unroll
        for (int ni = 0; ni < 4; ni++) {
            int m = rowBase + mi*16;
            int cn = colBase + ni*8;
            *(float2*)&F[(size_t)m * LD + cn]       = make_float2(acc[mi][ni][0], acc[mi][ni][1]);
            *(float2*)&F[(size_t)(m + 8) * LD + cn] = make_float2(acc[mi][ni][2], acc[mi][ni][3]);
        }
    }
}

// ---------------------------------------------------------------------------
// Einsum with Hermitian weight projection; outputs split-bf16 H.
__global__ void __launch_bounds__(256) k_einsum_h(const float* __restrict__ w) {
    int k2 = blockIdx.x * 256 + threadIdx.x;       // 0..511
    int k1 = blockIdx.y;                           // 0..255
    if (k2 == 511) {
        #pragma unroll
        for (int bo = 0; bo < 32; bo++) {
            int idx = bo * (HH*LD) + k1 * LD + 511;
            g_Hrh[idx] = __float2bfloat16(0.f); g_Hrl[idx] = __float2bfloat16(0.f);
            g_Hih[idx] = __float2bfloat16(0.f); g_Hil[idx] = __float2bfloat16(0.f);
        }
        return;
    }
    float fr[16], fi[16];
    {
        int off = k1 * LD + k2;
        #pragma unroll
        for (int bc = 0; bc < 16; bc++) {
            fr[bc] = g_Fr[bc * (HH*LD) + off];
            fi[bc] = g_Fi[bc * (HH*LD) + off];
        }
    }
    const int m1 = (k1 == 0) ? 0 : (NF - k1);
    const int m2 = (k2 == 0) ? 0 : (NF - k2);
    const int wbase  = (k1 * NF + k2) * 2;
    const int wmbase = (m1 * NF + m2) * 2;
    const float s = (k1 == 0) ? 0.5f : 1.0f;
    const int hidx = k1 * LD + k2;
    #pragma unroll
    for (int o = 0; o < 8; o++) {
        float whr[4], whi[4];
        #pragma unroll
        for (int cc = 0; cc < 4; cc++) {
            int base  = (o * 4 + cc) * (NN2 * 2);
            float w1r = w[base + wbase],  w1i = w[base + wbase + 1];
            float w2r = w[base + wmbase], w2i = w[base + wmbase + 1];
            whr[cc] = s * (w1r + w2r);
            whi[cc] = s * (w1i - w2i);
        }
        #pragma unroll
        for (int b = 0; b < 4; b++) {
            float ar = 0.f, ai = 0.f;
            #pragma unroll
            for (int cc = 0; cc < 4; cc++) {
                float xr = fr[b*4+cc], xi = fi[b*4+cc];
                ar += xr * whr[cc] - xi * whi[cc];
                ai += xr * whi[cc] + xi * whr[cc];
            }
            int idx = (b * 8 + o) * (HH*LD) + hidx;
            split_store(g_Hrh, g_Hrl, idx, ar);
            split_store(g_Hih, g_Hil, idx, ai);
        }
    }
}

// ---------------------------------------------------------------------------
// inv_u: C[256, 512] = A[256, 3072]*B[512, 3072]^T per bo; transposed U out.
// grid (4 ntile, 2 mtile, 32 batch), 512 threads.
__global__ void __launch_bounds__(NT) k_inv_u_mma() {
    extern __shared__ char dyn_smem[];
    char* base = (char*)(((uintptr_t)dyn_smem + 127) & ~(uintptr_t)127);
    const uint32_t tiles = smem_u32(base);
    GEMM_IDX
    const int ntile = blockIdx.x, mtile = blockIdx.y, batch = blockIdx.z;

    const size_t hB = (size_t)batch * (HH * LD);
    const __nv_bfloat16* Ablk[6] = { g_Hrh + hB, g_Hih + hB, g_Hrl + hB,
                                     g_Hil + hB, g_Hrh + hB, g_Hih + hB };
    const __nv_bfloat16* Bblk[6] = { g_Brh, g_Bih, g_Brh, g_Bih, g_Brl, g_Bil };

    const size_t aGbase = (size_t)(mtile*128 + grow) * LD + gseg*16;
    const size_t bGbase = (size_t)(ntile*128 + grow) * LD + gseg*16;

    ACC_INIT
    gemm_loop<48, 3>(Ablk, Bblk, aGbase, bGbase, tiles, sOff, aFrag, bFrag, acc);

    const int group = lane >> 2, tid4 = lane & 3;
    const bool isR = (ntile < 2);
    __nv_bfloat16* Th = (isR ? g_UrTh : g_UiTh) + (size_t)batch * (HH*HH);
    __nv_bfloat16* Tl = (isR ? g_UrTl : g_UiTl) + (size_t)batch * (HH*HH);
    const int colBase = (ntile & 1) * 128 + wn*32 + tid4*2;
    const int rowBase = mtile*128 + wm*32 + group;
    #pragma unroll
    for (int mi = 0; mi < 2; mi++) {
        #pragma unroll
        for (int ni = 0; ni < 4; ni++) {
            int m = rowBase + mi*16;
            int cn = colBase + ni*8;
            split_store(Th, Tl, (size_t)cn * HH + m,           acc[mi][ni][0]);
            split_store(Th, Tl, (size_t)(cn + 1) * HH + m,     acc[mi][ni][1]);
            split_store(Th, Tl, (size_t)cn * HH + m + 8,       acc[mi][ni][2]);
            split_store(Th, Tl, (size_t)(cn + 1) * HH + m + 8, acc[mi][ni][3]);
        }
    }
}

// ---------------------------------------------------------------------------
// k_out: out = scale * (A[256,1536]*B[256,1536]^T) + bias.
// grid (2 ntile, 2 mtile, 32 batch), 512 threads.
__global__ void __launch_bounds__(NT) k_out_mma(const float* __restrict__ bias,
                                               float* __restrict__ out) {
    extern __shared__ char dyn_smem[];
    char* base = (char*)(((uintptr_t)dyn_smem + 127) & ~(uintptr_t)127);
    const uint32_t tiles = smem_u32(base);
    GEMM_IDX
    const int ntile = blockIdx.x, mtile = blockIdx.y, batch = blockIdx.z;
    const float scale = 1.0f / ((float)NF * (float)NF);
    const float bias_v = bias[batch & 7];

    const size_t uB = (size_t)batch * (HH * HH);
    const __nv_bfloat16* Ablk[6] = { g_sTrh, g_sTih, g_sTrl, g_sTil, g_sTrh, g_sTih };
    const __nv_bfloat16* Bblk[6] = { g_UrTh + uB, g_UiTh + uB, g_UrTh + uB,
                                     g_UiTh + uB, g_UrTl + uB, g_UiTl + uB };

    const size_t aGbase = (size_t)(CROP0 + mtile*128 + grow) * HH + gseg*16;
    const size_t bGbase = (size_t)(ntile*128 + grow) * HH + gseg*16;

    ACC_INIT
    gemm_loop<24, 2>(Ablk, Bblk, aGbase, bGbase, tiles, sOff, aFrag, bFrag, acc);

    const int group = lane >> 2, tid4 = lane & 3;
    float* C = out + (size_t)batch * (HH*HH);
    const int colBase = ntile*128 + wn*32 + tid4*2;
    const int rowBase = mtile*128 + wm*32 + group;
    #pragma unroll
    for (int mi = 0; mi < 2; mi++) {
        #pragma unroll
        for (int ni = 0; ni < 4; ni++) {
            int m = rowBase + mi*16;
            int cn = colBase + ni*8;
            *(float2*)&C[(size_t)m * HH + cn] =
                make_float2(acc[mi][ni][0]*scale + bias_v, acc[mi][ni][1]*scale + bias_v);
            *(float2*)&C[(size_t)(m + 8) * HH + cn] =
                make_float2(acc[mi][ni][2]*scale + bias_v, acc[mi][ni][3]*scale + bias_v);
        }
    }
}

// ---------------------------------------------------------------------------
extern "C" void kernel_launch(void* const* d_in, const int* in_sizes, int n_in,
                              void* d_out, int out_size) {
    const float* im   = (const float*)d_in[0];   // (4,4,256,256)
    const float* wgt  = (const float*)d_in[1];   // (8,4,511,511,2)
    const float* bias = (const float*)d_in[2];   // (8,1,1)
    float* out = (float*)d_out;                  // (4,8,256,256)

    static int smem_set = 0;
    if (!smem_set) {
        cudaFuncSetAttribute(k_fwd_cols_mma, cudaFuncAttributeMaxDynamicSharedMemorySize, MMA_SMEM);
        cudaFuncSetAttribute(k_fwd_rows_mma, cudaFuncAttributeMaxDynamicSharedMemorySize, MMA_SMEM);
        cudaFuncSetAttribute(k_inv_u_mma,    cudaFuncAttributeMaxDynamicSharedMemorySize, MMA_SMEM);
        cudaFuncSetAttribute(k_out_mma,      cudaFuncAttributeMaxDynamicSharedMemorySize, MMA_SMEM);
        smem_set = 1;
    }

    k_prep_ops    <<<(524288) / 256, 256>>>();
    k_prep_x      <<<dim3(8, 8, 16), dim3(32, 8)>>>(im);
    k_fwd_cols_mma<<<dim3(2, 4, 16), NT, MMA_SMEM>>>();
    k_fwd_rows_mma<<<dim3(8, 2, 16), NT, MMA_SMEM>>>();
    k_einsum_h    <<<dim3(2, 256),   256>>>(wgt);
    k_inv_u_mma   <<<dim3(4, 2, 32), NT, MMA_SMEM>>>();
    k_out_mma     <<<dim3(2, 2, 32), NT, MMA_SMEM>>>(bias, out);
}

// round 15
// speedup vs baseline: 1.3374x; 1.0502x over previous
#include <cuda_runtime.h>
#include <cuda_bf16.h>
#include <math_constants.h>
#include <cstdint>

// FourierConv2D via DFT matmuls. ALL four GEMMs on mma.sync bf16
// split-precision (hi/lo, lo*lo dropped), cp.async double-buffered mainloop,
// 512 threads / 16 warps per CTA (32x32 per warp), 128x128 CTA tiles,
// __launch_bounds__(512, 2) to force 2 CTAs/SM (32 resident warps).

#define NF 511
#define LD 512
#define HH 256
#define CROP0 127
#define NN2 (NF*NF)

// ---- scratch (device globals) ----
__device__ __nv_bfloat16 g_A1h[LD*HH], g_A1l[LD*HH];
__device__ __nv_bfloat16 g_xTh[16*HH*HH], g_xTl[16*HH*HH];
__device__ __nv_bfloat16 g_T1rh[16*HH*HH], g_T1rl[16*HH*HH];
__device__ __nv_bfloat16 g_T1ih[16*HH*HH], g_T1il[16*HH*HH];
__device__ __nv_bfloat16 g_Ph[1024*HH], g_Pl[1024*HH];
__device__ __nv_bfloat16 g_Qh[1024*HH], g_Ql[1024*HH];
__device__ __nv_bfloat16 g_sTrh[LD*HH], g_sTrl[LD*HH];
__device__ __nv_bfloat16 g_sTih[LD*HH], g_sTil[LD*HH];
__device__ float g_Fr[16*HH*LD], g_Fi[16*HH*LD];
__device__ __nv_bfloat16 g_Hrh[32*HH*LD], g_Hrl[32*HH*LD];
__device__ __nv_bfloat16 g_Hih[32*HH*LD], g_Hil[32*HH*LD];
__device__ __nv_bfloat16 g_Brh[LD*LD], g_Bih[LD*LD], g_Brl[LD*LD], g_Bil[LD*LD];
__device__ __nv_bfloat16 g_UrTh[32*HH*HH], g_UrTl[32*HH*HH];
__device__ __nv_bfloat16 g_UiTh[32*HH*HH], g_UiTl[32*HH*HH];

// ---- helpers ----
__device__ __forceinline__ void split_bf16(float v, __nv_bfloat16 &h, __nv_bfloat16 &l) {
    h = __float2bfloat16(v);
    l = __float2bfloat16(v - __bfloat162float(h));
}
__device__ __forceinline__ void split_store(__nv_bfloat16* H, __nv_bfloat16* L,
                                            size_t idx, float v) {
    __nv_bfloat16 h, l; split_bf16(v, h, l); H[idx] = h; L[idx] = l;
}
__device__ __forceinline__ void twiddle_ab(int a, int b, float &cr, float &ci) {
    if (a >= NF || b >= NF) { cr = 0.f; ci = 0.f; return; }
    int r = (a * b) % NF;
    float ang = (-2.0f * CUDART_PI_F / (float)NF) * (float)r;
    sincosf(ang, &ci, &cr);
}

__device__ __forceinline__ uint32_t smem_u32(const void* p) {
    uint32_t a;
    asm("{ .reg .u64 t; cvta.to.shared.u64 t, %1; cvt.u32.u64 %0, t; }" : "=r"(a) : "l"(p));
    return a;
}
__device__ __forceinline__ void cp_async16(uint32_t dst, const void* src) {
    asm volatile("cp.async.cg.shared.global [%0], [%1], 16;" :: "r"(dst), "l"(src));
}
#define CP_COMMIT() asm volatile("cp.async.commit_group;" ::: "memory")
#define CP_WAIT0()  asm volatile("cp.async.wait_group 0;" ::: "memory")

__device__ __forceinline__ void ldsm_x4(uint32_t &r0, uint32_t &r1, uint32_t &r2, uint32_t &r3,
                                        uint32_t addr) {
    asm volatile("ldmatrix.sync.aligned.m8n8.x4.shared.b16 {%0,%1,%2,%3}, [%4];"
                 : "=r"(r0), "=r"(r1), "=r"(r2), "=r"(r3) : "r"(addr));
}
__device__ __forceinline__ void ldsm_x2(uint32_t &r0, uint32_t &r1, uint32_t addr) {
    asm volatile("ldmatrix.sync.aligned.m8n8.x2.shared.b16 {%0,%1}, [%2];"
                 : "=r"(r0), "=r"(r1) : "r"(addr));
}
__device__ __forceinline__ void mma_bf16(float* c, const uint32_t* a, const uint32_t* b) {
    asm volatile("mma.sync.aligned.m16n8k16.row.col.f32.bf16.bf16.f32 "
                 "{%0,%1,%2,%3}, {%4,%5,%6,%7}, {%8,%9}, {%0,%1,%2,%3};"
                 : "+f"(c[0]), "+f"(c[1]), "+f"(c[2]), "+f"(c[3])
                 : "r"(a[0]), "r"(a[1]), "r"(a[2]), "r"(a[3]), "r"(b[0]), "r"(b[1]));
}

#define KC 64
#define ROWB 144
#define TILEB (128 * ROWB)          // 18432 per operand tile
#define BUFB  (2 * TILEB)           // 36864 per stage (A + B)
#define MMA_SMEM (2 * BUFB + 128)   // 73856 -> 2 CTAs/SM
#define NT 512                      // 16 warps: 4x4 grid, 32x32 tile each

// Shared GEMM mainloop: C_tile(128x128), 16 warps, cp.async double-buffered.
// Thread t loads row t>>2 (0..127), 32B segment (t&3) of both A and B rows.
template<int NCH, int LOG2>
__device__ __forceinline__ void gemm_loop(
    const __nv_bfloat16* const* Ablk, const __nv_bfloat16* const* Bblk,
    size_t aGbase, size_t bGbase,
    uint32_t tiles, uint32_t sOff, uint32_t aFrag, uint32_t bFrag,
    float acc[2][4][4])
{
    {   // prologue: chunk 0 into buf 0
        const __nv_bfloat16* Ag = Ablk[0] + aGbase;
        const __nv_bfloat16* Bg = Bblk[0] + bGbase;
        uint32_t aT = tiles + sOff;
        uint32_t bT = aT + TILEB;
        cp_async16(aT,      Ag);
        cp_async16(aT + 16, Ag + 8);
        cp_async16(bT,      Bg);
        cp_async16(bT + 16, Bg + 8);
        CP_COMMIT();
    }
    for (int c = 0; c < NCH; c++) {
        CP_WAIT0();
        __syncthreads();
        if (c + 1 < NCH) {
            const int blk = (c + 1) >> LOG2;
            const int k0  = ((c + 1) & ((1 << LOG2) - 1)) * KC;
            const __nv_bfloat16* Ag = Ablk[blk] + aGbase + k0;
            const __nv_bfloat16* Bg = Bblk[blk] + bGbase + k0;
            uint32_t aT = tiles + ((c + 1) & 1) * BUFB + sOff;
            uint32_t bT = aT + TILEB;
            cp_async16(aT,      Ag);
            cp_async16(aT + 16, Ag + 8);
            cp_async16(bT,      Bg);
            cp_async16(bT + 16, Bg + 8);
            CP_COMMIT();
        }
        const uint32_t aBase = tiles + (c & 1) * BUFB + aFrag;
        const uint32_t bBase = tiles + (c & 1) * BUFB + TILEB + bFrag;
        #pragma unroll
        for (int kk = 0; kk < 4; kk++) {
            uint32_t af[2][4], bf[4][2];
            #pragma unroll
            for (int mi = 0; mi < 2; mi++)
                ldsm_x4(af[mi][0], af[mi][1], af[mi][2], af[mi][3],
                        aBase + mi * (16 * ROWB) + kk * 32);
            #pragma unroll
            for (int ni = 0; ni < 4; ni++)
                ldsm_x2(bf[ni][0], bf[ni][1], bBase + ni * (8 * ROWB) + kk * 32);
            #pragma unroll
            for (int mi = 0; mi < 2; mi++)
                #pragma unroll
                for (int ni = 0; ni < 4; ni++)
                    mma_bf16(acc[mi][ni], af[mi], bf[ni]);
        }
    }
}

// Per-thread GEMM indices for NT=512 blocks, 128x128 tiles.
#define GEMM_IDX                                                             \
    const int t = threadIdx.x, lane = t & 31, wid = t >> 5;                  \
    const int wm = wid >> 2, wn = wid & 3;          /* 4x4 warp grid */      \
    const int grow = t >> 2, gseg = t & 3;                                   \
    const uint32_t sOff = (uint32_t)(grow * ROWB + gseg * 32);               \
    const uint32_t aFrag = (uint32_t)((wm*32 + (lane & 15)) * ROWB + (lane >> 4) * 16); \
    const uint32_t bFrag = (uint32_t)((wn*32 + (lane & 7)) * ROWB + ((lane >> 3) & 1) * 16);

#define ACC_INIT                                                             \
    float acc[2][4][4];                                                      \
    _Pragma("unroll")                                                        \
    for (int i = 0; i < 2; i++)                                              \
        _Pragma("unroll")                                                    \
        for (int j = 0; j < 4; j++)                                          \
            _Pragma("unroll")                                                \
            for (int q = 0; q < 4; q++) acc[i][j][q] = 0.f;

// ---------------------------------------------------------------------------
// Merged operand prep: ids [0, 262144) -> inv_u B operand (512x512),
// ids [262144, 524288) -> P/Q + split twiddle + A1 (1024x256).
__global__ void __launch_bounds__(256) k_prep_ops() {
    int gid = blockIdx.x * 256 + threadIdx.x;
    if (gid < 262144) {
        int p = gid;                        // 512*512
        int n = p >> 9, k = p & 511;
        int row = CROP0 + ((n < 256) ? n : (n - 256));
        float tr, ti;
        twiddle_ab(row, k, tr, ti);
        float br = (n < 256) ? tr : -ti;
        float bi = (n < 256) ? ti :  tr;
        split_store(g_Brh, g_Brl, p, br);
        split_store(g_Bih, g_Bil, p, bi);
    } else {
        int p = gid - 262144;               // 1024*256
        int n = p >> 8, k = p & 255;
        if (n < 512) {
            float tr, ti;
            twiddle_ab(n, k, tr, ti);
            split_store(g_sTrh, g_sTrl, p, tr);
            split_store(g_sTih, g_sTil, p, ti);
            split_store(g_Ph, g_Pl, p, tr);
            split_store(g_Qh, g_Ql, p, -ti);
            if (n < 256) split_store(g_A1h, g_A1l, p, tr);
            else {
                float tr2, ti2;
                twiddle_ab(n - 256, k, tr2, ti2);
                split_store(g_A1h, g_A1l, p, ti2);
            }
        } else {
            float tr, ti;
            twiddle_ab(n - 512, k, tr, ti);
            split_store(g_Ph, g_Pl, p, ti);
            split_store(g_Qh, g_Ql, p, tr);
        }
    }
}

__global__ void __launch_bounds__(256) k_prep_x(const float* __restrict__ x) {
    __shared__ float tile[32][33];
    const int bc = blockIdx.z;
    const int n10 = blockIdx.x * 32, n20 = blockIdx.y * 32;
    const float* X = x + (size_t)bc * (HH*HH);
    #pragma unroll
    for (int r = 0; r < 4; r++) {
        int n1 = n10 + threadIdx.y + r*8;
        tile[threadIdx.y + r*8][threadIdx.x] = X[(size_t)n1 * HH + n20 + threadIdx.x];
    }
    __syncthreads();
    const size_t ob = (size_t)bc * (HH*HH);
    #pragma unroll
    for (int r = 0; r < 4; r++) {
        int n2 = n20 + threadIdx.y + r*8;
        split_store(g_xTh, g_xTl, ob + (size_t)n2 * HH + n10 + threadIdx.x,
                    tile[threadIdx.x][threadIdx.y + r*8]);
    }
}

// ---------------------------------------------------------------------------
// fwd_cols: C[512, 256] = A[512, 768]*B[256, 768]^T per bc.
// grid (2 ntile, 4 mtile, 16 batch), 512 threads.
__global__ void __launch_bounds__(NT, 2) k_fwd_cols_mma() {
    extern __shared__ char dyn_smem[];
    char* base = (char*)(((uintptr_t)dyn_smem + 127) & ~(uintptr_t)127);
    const uint32_t tiles = smem_u32(base);
    GEMM_IDX
    const int ntile = blockIdx.x, mtile = blockIdx.y, batch = blockIdx.z;

    const size_t xB = (size_t)batch * (HH * HH);
    const __nv_bfloat16* Ablk[3] = { g_A1h, g_A1l, g_A1h };
    const __nv_bfloat16* Bblk[3] = { g_xTh + xB, g_xTh + xB, g_xTl + xB };

    const size_t aGbase = (size_t)(mtile*128 + grow) * HH + gseg*16;
    const size_t bGbase = (size_t)(ntile*128 + grow) * HH + gseg*16;

    ACC_INIT
    gemm_loop<12, 2>(Ablk, Bblk, aGbase, bGbase, tiles, sOff, aFrag, bFrag, acc);

    const int group = lane >> 2, tid4 = lane & 3;
    const bool isR = (mtile < 2);
    __nv_bfloat16* Th = (isR ? g_T1rh : g_T1ih) + xB;
    __nv_bfloat16* Tl = (isR ? g_T1rl : g_T1il) + xB;
    const int colBase = ntile*128 + wn*32 + tid4*2;
    const int rowBase = (mtile & 1)*128 + wm*32 + group;
    #pragma unroll
    for (int mi = 0; mi < 2; mi++) {
        #pragma unroll
        for (int ni = 0; ni < 4; ni++) {
            int m = rowBase + mi*16;
            int cn = colBase + ni*8;
            split_store(Th, Tl, (size_t)m * HH + cn,           acc[mi][ni][0]);
            split_store(Th, Tl, (size_t)m * HH + cn + 1,       acc[mi][ni][1]);
            split_store(Th, Tl, (size_t)(m + 8) * HH + cn,     acc[mi][ni][2]);
            split_store(Th, Tl, (size_t)(m + 8) * HH + cn + 1, acc[mi][ni][3]);
        }
    }
}

// ---------------------------------------------------------------------------
// fwd_rows: C[256, 1024] = A[256, 1536]*B[1024, 1536]^T per bc.
// grid (8 ntile, 2 mtile, 16 batch), 512 threads.
__global__ void __launch_bounds__(NT, 2) k_fwd_rows_mma() {
    extern __shared__ char dyn_smem[];
    char* base = (char*)(((uintptr_t)dyn_smem + 127) & ~(uintptr_t)127);
    const uint32_t tiles = smem_u32(base);
    GEMM_IDX
    const int ntile = blockIdx.x, mtile = blockIdx.y, batch = blockIdx.z;

    const size_t aB = (size_t)batch * (HH * HH);
    const __nv_bfloat16* Ablk[6] = { g_T1rh + aB, g_T1ih + aB, g_T1rl + aB,
                                     g_T1il + aB, g_T1rh + aB, g_T1ih + aB };
    const __nv_bfloat16* Bblk[6] = { g_Ph, g_Qh, g_Ph, g_Qh, g_Pl, g_Ql };

    const size_t aGbase = (size_t)(mtile*128 + grow) * HH + gseg*16;
    const size_t bGbase = (size_t)(ntile*128 + grow) * HH + gseg*16;

    ACC_INIT
    gemm_loop<24, 2>(Ablk, Bblk, aGbase, bGbase, tiles, sOff, aFrag, bFrag, acc);

    const int group = lane >> 2, tid4 = lane & 3;
    float* F = ((ntile < 4) ? g_Fr : g_Fi) + (size_t)batch * (HH*LD);
    const int colBase = (ntile & 3) * 128 + wn*32 + tid4*2;
    const int rowBase = mtile*128 + wm*32 + group;
    #pragma unroll
    for (int mi = 0; mi < 2; mi++) {
        #pragma unroll
        for (int ni = 0; ni < 4; ni++) {
            int m = rowBase + mi*16;
            int cn = colBase + ni*8;
            *(float2*)&F[(size_t)m * LD + cn]       = make_float2(acc[mi][ni][0], acc[mi][ni][1]);
            *(float2*)&F[(size_t)(m + 8) * LD + cn] = make_float2(acc[mi][ni][2], acc[mi][ni][3]);
        }
    }
}

// ---------------------------------------------------------------------------
// Einsum with Hermitian weight projection; outputs split-bf16 H.
__global__ void __launch_bounds__(256) k_einsum_h(const float* __restrict__ w) {
    int k2 = blockIdx.x * 256 + threadIdx.x;       // 0..511
    int k1 = blockIdx.y;                           // 0..255
    if (k2 == 511) {
        #pragma unroll
        for (int bo = 0; bo < 32; bo++) {
            int idx = bo * (HH*LD) + k1 * LD + 511;
            g_Hrh[idx] = __float2bfloat16(0.f); g_Hrl[idx] = __float2bfloat16(0.f);
            g_Hih[idx] = __float2bfloat16(0.f); g_Hil[idx] = __float2bfloat16(0.f);
        }
        return;
    }
    float fr[16], fi[16];
    {
        int off = k1 * LD + k2;
        #pragma unroll
        for (int bc = 0; bc < 16; bc++) {
            fr[bc] = g_Fr[bc * (HH*LD) + off];
            fi[bc] = g_Fi[bc * (HH*LD) + off];
        }
    }
    const int m1 = (k1 == 0) ? 0 : (NF - k1);
    const int m2 = (k2 == 0) ? 0 : (NF - k2);
    const int wbase  = (k1 * NF + k2) * 2;
    const int wmbase = (m1 * NF + m2) * 2;
    const float s = (k1 == 0) ? 0.5f : 1.0f;
    const int hidx = k1 * LD + k2;
    #pragma unroll
    for (int o = 0; o < 8; o++) {
        float whr[4], whi[4];
        #pragma unroll
        for (int cc = 0; cc < 4; cc++) {
            int base  = (o * 4 + cc) * (NN2 * 2);
            float w1r = w[base + wbase],  w1i = w[base + wbase + 1];
            float w2r = w[base + wmbase], w2i = w[base + wmbase + 1];
            whr[cc] = s * (w1r + w2r);
            whi[cc] = s * (w1i - w2i);
        }
        #pragma unroll
        for (int b = 0; b < 4; b++) {
            float ar = 0.f, ai = 0.f;
            #pragma unroll
            for (int cc = 0; cc < 4; cc++) {
                float xr = fr[b*4+cc], xi = fi[b*4+cc];
                ar += xr * whr[cc] - xi * whi[cc];
                ai += xr * whi[cc] + xi * whr[cc];
            }
            int idx = (b * 8 + o) * (HH*LD) + hidx;
            split_store(g_Hrh, g_Hrl, idx, ar);
            split_store(g_Hih, g_Hil, idx, ai);
        }
    }
}

// ---------------------------------------------------------------------------
// inv_u: C[256, 512] = A[256, 3072]*B[512, 3072]^T per bo; transposed U out.
// grid (4 ntile, 2 mtile, 32 batch), 512 threads.
__global__ void __launch_bounds__(NT, 2) k_inv_u_mma() {
    extern __shared__ char dyn_smem[];
    char* base = (char*)(((uintptr_t)dyn_smem + 127) & ~(uintptr_t)127);
    const uint32_t tiles = smem_u32(base);
    GEMM_IDX
    const int ntile = blockIdx.x, mtile = blockIdx.y, batch = blockIdx.z;

    const size_t hB = (size_t)batch * (HH * LD);
    const __nv_bfloat16* Ablk[6] = { g_Hrh + hB, g_Hih + hB, g_Hrl + hB,
                                     g_Hil + hB, g_Hrh + hB, g_Hih + hB };
    const __nv_bfloat16* Bblk[6] = { g_Brh, g_Bih, g_Brh, g_Bih, g_Brl, g_Bil };

    const size_t aGbase = (size_t)(mtile*128 + grow) * LD + gseg*16;
    const size_t bGbase = (size_t)(ntile*128 + grow) * LD + gseg*16;

    ACC_INIT
    gemm_loop<48, 3>(Ablk, Bblk, aGbase, bGbase, tiles, sOff, aFrag, bFrag, acc);

    const int group = lane >> 2, tid4 = lane & 3;
    const bool isR = (ntile < 2);
    __nv_bfloat16* Th = (isR ? g_UrTh : g_UiTh) + (size_t)batch * (HH*HH);
    __nv_bfloat16* Tl = (isR ? g_UrTl : g_UiTl) + (size_t)batch * (HH*HH);
    const int colBase = (ntile & 1) * 128 + wn*32 + tid4*2;
    const int rowBase = mtile*128 + wm*32 + group;
    #pragma unroll
    for (int mi = 0; mi < 2; mi++) {
        #pragma unroll
        for (int ni = 0; ni < 4; ni++) {
            int m = rowBase + mi*16;
            int cn = colBase + ni*8;
            split_store(Th, Tl, (size_t)cn * HH + m,           acc[mi][ni][0]);
            split_store(Th, Tl, (size_t)(cn + 1) * HH + m,     acc[mi][ni][1]);
            split_store(Th, Tl, (size_t)cn * HH + m + 8,       acc[mi][ni][2]);
            split_store(Th, Tl, (size_t)(cn + 1) * HH + m + 8, acc[mi][ni][3]);
        }
    }
}

// ---------------------------------------------------------------------------
// k_out: out = scale * (A[256,1536]*B[256,1536]^T) + bias.
// grid (2 ntile, 2 mtile, 32 batch), 512 threads.
__global__ void __launch_bounds__(NT, 2) k_out_mma(const float* __restrict__ bias,
                                                  float* __restrict__ out) {
    extern __shared__ char dyn_smem[];
    char* base = (char*)(((uintptr_t)dyn_smem + 127) & ~(uintptr_t)127);
    const uint32_t tiles = smem_u32(base);
    GEMM_IDX
    const int ntile = blockIdx.x, mtile = blockIdx.y, batch = blockIdx.z;
    const float scale = 1.0f / ((float)NF * (float)NF);
    const float bias_v = bias[batch & 7];

    const size_t uB = (size_t)batch * (HH * HH);
    const __nv_bfloat16* Ablk[6] = { g_sTrh, g_sTih, g_sTrl, g_sTil, g_sTrh, g_sTih };
    const __nv_bfloat16* Bblk[6] = { g_UrTh + uB, g_UiTh + uB, g_UrTh + uB,
                                     g_UiTh + uB, g_UrTl + uB, g_UiTl + uB };

    const size_t aGbase = (size_t)(CROP0 + mtile*128 + grow) * HH + gseg*16;
    const size_t bGbase = (size_t)(ntile*128 + grow) * HH + gseg*16;

    ACC_INIT
    gemm_loop<24, 2>(Ablk, Bblk, aGbase, bGbase, tiles, sOff, aFrag, bFrag, acc);

    const int group = lane >> 2, tid4 = lane & 3;
    float* C = out + (size_t)batch * (HH*HH);
    const int colBase = ntile*128 + wn*32 + tid4*2;
    const int rowBase = mtile*128 + wm*32 + group;
    #pragma unroll
    for (int mi = 0; mi < 2; mi++) {
        #pragma unroll
        for (int ni = 0; ni < 4; ni++) {
            int m = rowBase + mi*16;
            int cn = colBase + ni*8;
            *(float2*)&C[(size_t)m * HH + cn] =
                make_float2(acc[mi][ni][0]*scale + bias_v, acc[mi][ni][1]*scale + bias_v);
            *(float2*)&C[(size_t)(m + 8) * HH + cn] =
                make_float2(acc[mi][ni][2]*scale + bias_v, acc[mi][ni][3]*scale + bias_v);
        }
    }
}

// ---------------------------------------------------------------------------
extern "C" void kernel_launch(void* const* d_in, const int* in_sizes, int n_in,
                              void* d_out, int out_size) {
    const float* im   = (const float*)d_in[0];   // (4,4,256,256)
    const float* wgt  = (const float*)d_in[1];   // (8,4,511,511,2)
    const float* bias = (const float*)d_in[2];   // (8,1,1)
    float* out = (float*)d_out;                  // (4,8,256,256)

    static int smem_set = 0;
    if (!smem_set) {
        cudaFuncSetAttribute(k_fwd_cols_mma, cudaFuncAttributeMaxDynamicSharedMemorySize, MMA_SMEM);
        cudaFuncSetAttribute(k_fwd_rows_mma, cudaFuncAttributeMaxDynamicSharedMemorySize, MMA_SMEM);
        cudaFuncSetAttribute(k_inv_u_mma,    cudaFuncAttributeMaxDynamicSharedMemorySize, MMA_SMEM);
        cudaFuncSetAttribute(k_out_mma,      cudaFuncAttributeMaxDynamicSharedMemorySize, MMA_SMEM);
        smem_set = 1;
    }

    k_prep_ops    <<<(524288) / 256, 256>>>();
    k_prep_x      <<<dim3(8, 8, 16), dim3(32, 8)>>>(im);
    k_fwd_cols_mma<<<dim3(2, 4, 16), NT, MMA_SMEM>>>();
    k_fwd_rows_mma<<<dim3(8, 2, 16), NT, MMA_SMEM>>>();
    k_einsum_h    <<<dim3(2, 256),   256>>>(wgt);
    k_inv_u_mma   <<<dim3(4, 2, 32), NT, MMA_SMEM>>>();
    k_out_mma     <<<dim3(2, 2, 32), NT, MMA_SMEM>>>(bias, out);
}